// round 16
// baseline (speedup 1.0000x reference)
#include <cuda_runtime.h>
#include <cstdint>

#define NB 32
#define NL 8192
#define NC 32
#define NF 32
#define TL 8                  // positions per CTA (= warps per CTA)
#define ROWS (TL + 3)         // halo: 2 before, 1 after
#define NSTG 2                // pipeline stages (per-position ring)
#define CCH 2                 // channels per chunk
#define NCHUNK (NC / CCH)     // 16 chunks
#define TAPCH_BYTES (CCH * NF * 4)        // 256 B per (tap,pos) chunk
#define POS_BYTES (5 * TAPCH_BYTES)       // 1280 B per pos per stage
#define STG_BYTES (TL * POS_BYTES)        // 10240 B per stage
#define MBAR_OFF 0                        // 8 pos * 32 B (2 full barriers each)
#define WS_OFF 512
#define SX_OFF (WS_OFF + NSTG * STG_BYTES)    // 20992
// x2 tile: batch-DUPLICATED rows, 64 floats (256 B) per (lp,c) row, rotation by 8c words
#define SX_BYTES (ROWS * NC * 64 * 4)         // 90112
#define SMEM_TOTAL (SX_OFF + SX_BYTES)        // 111104 -> 2 CTAs/SM

// Inter-layer scratch for h = leaky(bn(lc1(x)))
__device__ float g_h[(size_t)NB * NL * NC];

typedef unsigned long long ull;

__device__ __forceinline__ void fma2(ull& d, ull a, ull b) {
    asm("fma.rn.f32x2 %0, %1, %2, %0;" : "+l"(d) : "l"(a), "l"(b));
}
__device__ __forceinline__ ull add2(ull a, ull b) {
    ull r;
    asm("add.rn.f32x2 %0, %1, %2;" : "=l"(r) : "l"(a), "l"(b));
    return r;
}
__device__ __forceinline__ float2 unpk(ull v) {
    float2 f;
    asm("mov.b64 {%0, %1}, %2;" : "=f"(f.x), "=f"(f.y) : "l"(v));
    return f;
}
__device__ __forceinline__ float lky(float v) { return v >= 0.f ? v : 0.3f * v; }

__device__ __forceinline__ uint32_t s2u(const void* p) {
    uint32_t a;
    asm("{ .reg .u64 t; cvta.to.shared.u64 t, %1; cvt.u32.u64 %0, t; }" : "=r"(a) : "l"(p));
    return a;
}
__device__ __forceinline__ void mbar_init(uint32_t a, uint32_t c) {
    asm volatile("mbarrier.init.shared.b64 [%0], %1;" :: "r"(a), "r"(c) : "memory");
}
__device__ __forceinline__ void mbar_expect(uint32_t a, uint32_t tx) {
    asm volatile("mbarrier.arrive.expect_tx.shared.b64 _, [%0], %1;" :: "r"(a), "r"(tx) : "memory");
}
__device__ __forceinline__ uint32_t mbar_poll(uint32_t a, uint32_t ph) {
    uint32_t r;
    asm volatile(
        "{\n\t.reg .pred P;\n\t"
        "mbarrier.test_wait.parity.shared.b64 P, [%1], %2;\n\t"
        "selp.b32 %0, 1, 0, P;\n\t}"
        : "=r"(r) : "r"(a), "r"(ph) : "memory");
    return r;
}
__device__ __forceinline__ void mbar_wait(uint32_t a, uint32_t ph) {
    asm volatile(
        "{\n\t.reg .pred P;\n"
        "W%=:\n\tmbarrier.try_wait.parity.shared.b64 P, [%0], %1, 0x989680;\n\t"
        "@P bra D%=;\n\tbra W%=;\nD%=:\n\t}"
        :: "r"(a), "r"(ph) : "memory");
}
__device__ __forceinline__ void bulk_cp(uint32_t dst, const float* src, uint32_t bytes, uint32_t mbar) {
    asm volatile("cp.async.bulk.shared::cta.global.mbarrier::complete_tx::bytes [%0], [%1], %2, [%3];"
                 :: "r"(dst), "l"(src), "r"(bytes), "r"(mbar) : "memory");
}

// Dup-free tap update: 8 dup'd batches (4x LDS.128, rotated) times 2 natural
// weight pairs -> 16 fma2, ZERO register-duplication MOVs.
__device__ __forceinline__ void tap_fma(ull acc[8][2], const float* row,
                                        int o0, int o1, int o2, int o3,
                                        ull wa, ull wb) {
    ulonglong2 x01 = *reinterpret_cast<const ulonglong2*>(row + o0);
    ulonglong2 x23 = *reinterpret_cast<const ulonglong2*>(row + o1);
    ulonglong2 x45 = *reinterpret_cast<const ulonglong2*>(row + o2);
    ulonglong2 x67 = *reinterpret_cast<const ulonglong2*>(row + o3);
    fma2(acc[0][0], x01.x, wa); fma2(acc[0][1], x01.x, wb);
    fma2(acc[1][0], x01.y, wa); fma2(acc[1][1], x01.y, wb);
    fma2(acc[2][0], x23.x, wa); fma2(acc[2][1], x23.x, wb);
    fma2(acc[3][0], x23.y, wa); fma2(acc[3][1], x23.y, wb);
    fma2(acc[4][0], x45.x, wa); fma2(acc[4][1], x45.x, wb);
    fma2(acc[5][0], x45.y, wa); fma2(acc[5][1], x45.y, wb);
    fma2(acc[6][0], x67.x, wa); fma2(acc[6][1], x67.x, wb);
    fma2(acc[7][0], x67.y, wa); fma2(acc[7][1], x67.y, wb);
}

template <bool SECOND>
__global__ void __launch_bounds__(256, 2)
lc_kernel(const float* __restrict__ in,
          const float* __restrict__ wts,     // [K, L, C, F]
          const float* __restrict__ bias,    // [L, F]
          const float* __restrict__ gamma,
          const float* __restrict__ beta,
          const float* __restrict__ mean,
          const float* __restrict__ var,
          const float* __restrict__ residx,  // original x (L2 only)
          float* __restrict__ out)
{
    extern __shared__ char smem[];
    const uint32_t sbase = s2u(smem);
    float* sx = reinterpret_cast<float*>(smem + SX_OFF);

    const int tid  = threadIdx.x;
    const int warp = tid >> 5;
    const int lane = tid & 31;
    const int l0   = blockIdx.x * TL;
    const int l    = l0 + warp;                 // one warp = one position

    // 2 full barriers per position; no empty barriers (same-warp ring)
    if (tid < TL * NSTG) {
        int p = tid >> 1, s = tid & 1;
        mbar_init(sbase + MBAR_OFF + p * 32 + s * 16, 1);
    }
    __syncthreads();

    const uint32_t mb = sbase + MBAR_OFF + warp * 32;
    const size_t tapStride = (size_t)NL * NC * NF;
    const float* wl = wts + (size_t)l * NC * NF;
    const uint32_t wposdst = sbase + WS_OFF + warp * POS_BYTES;

    auto produce = [&](int slot, int chunk) {
        if (lane == 0) {
            mbar_expect(mb + slot * 16, POS_BYTES);
            #pragma unroll
            for (int k = 0; k < 5; ++k)
                bulk_cp(wposdst + slot * STG_BYTES + k * TAPCH_BYTES,
                        wl + (size_t)k * tapStride + chunk * (CCH * NF),
                        TAPCH_BYTES, mb + slot * 16);
        }
    };

    produce(0, 0);
    produce(1, 1);

    // Stage batch-DUPLICATED x tile while weight DMA is in flight.
    // Layout: row (lp*NC + c) is 64 words; batch b occupies words
    // (2b + 8c) & 63 and +1 (rotation kills the 256B-stride bank collisions).
    // Thread mapping: lanes cover 8 consecutive c x 4 b-spread-by-8
    // -> LDG: 4 fully-used 32B sectors; STS.64: <=4-way conflicts.
    const float* src = SECOND ? (const float*)g_h : in;
    for (int j = tid; j < NB * ROWS * NC; j += 256) {
        int c  = (j & 7) | (((j >> 5) & 3) << 3);
        int b  = ((j >> 3) & 3) * 8 + ((j >> 7) & 7);
        int lp = j >> 10;
        int gl = (l0 + lp - 2) & (NL - 1);
        float v = src[((size_t)b * NL + gl) * NC + c];
        int w = (2 * b + 8 * c) & 63;
        *reinterpret_cast<float2*>(sx + ((lp * NC + c) << 6) + w) = make_float2(v, v);
    }
    __syncthreads();

    const int f0 = (lane & 7) << 2;             // 4 filters / thread (2 f-pairs)
    const int b0 = (lane >> 3) << 3;            // 8 batches / thread

    ull acc[8][2];
    #pragma unroll
    for (int i = 0; i < 8; ++i) { acc[i][0] = 0ull; acc[i][1] = 0ull; }

    // Row bases per tap (row length 64 words)
    const float* rw2 = sx + ((warp + 2) * NC) * 64;   // taps 0+1 (merged)
    const float* rw1 = sx + ((warp + 1) * NC) * 64;   // tap 2
    const float* rw3 = sx + ((warp + 3) * NC) * 64;   // tap 3
    const float* rw0 = sx + ((warp + 0) * NC) * 64;   // tap 4
    const char*  wsb = smem + WS_OFF + warp * POS_BYTES + f0 * 4;

    auto consume = [&](int slot, int chunk) {
        const char* wp0 = wsb + slot * STG_BYTES;
        #pragma unroll
        for (int cc = 0; cc < CCH; ++cc) {
            const int c = chunk * CCH + cc;
            // natural weight pairs: float4 -> 2 ull, no MOVs
            ulonglong2 wA = *reinterpret_cast<const ulonglong2*>(wp0 + 0 * TAPCH_BYTES + cc * 128);
            ulonglong2 wB = *reinterpret_cast<const ulonglong2*>(wp0 + 1 * TAPCH_BYTES + cc * 128);
            ulonglong2 wC = *reinterpret_cast<const ulonglong2*>(wp0 + 2 * TAPCH_BYTES + cc * 128);
            ulonglong2 wD = *reinterpret_cast<const ulonglong2*>(wp0 + 3 * TAPCH_BYTES + cc * 128);
            ulonglong2 wE = *reinterpret_cast<const ulonglong2*>(wp0 + 4 * TAPCH_BYTES + cc * 128);
            ull m0 = add2(wA.x, wB.x), m1 = add2(wA.y, wB.y);   // taps 0+1 merged

            const int base = 2 * b0 + 8 * c;
            const int o0 = (base     ) & 63, o1 = (base +  4) & 63;
            const int o2 = (base +  8) & 63, o3 = (base + 12) & 63;
            const int rofs = c * 64;

            tap_fma(acc, rw2 + rofs, o0, o1, o2, o3, m0, m1);
            tap_fma(acc, rw1 + rofs, o0, o1, o2, o3, wC.x, wC.y);
            tap_fma(acc, rw3 + rofs, o0, o1, o2, o3, wD.x, wD.y);
            tap_fma(acc, rw0 + rofs, o0, o1, o2, o3, wE.x, wE.y);
        }
    };

    // Wait for chunk 0 (slot 0, phase 0)
    mbar_wait(mb, 0u);

    // Steady state, unrolled by 2 (R14 protocol: poll-ahead, late wait)
    #pragma unroll 1
    for (int it = 0; it < NCHUNK / 2 - 1; ++it) {
        const uint32_t ph = (uint32_t)(it & 1);

        uint32_t rdy = mbar_poll(mb + 16, ph);
        consume(0, 2 * it);
        produce(0, 2 * it + 2);
        if (!rdy) mbar_wait(mb + 16, ph);

        uint32_t rdy2 = mbar_poll(mb, ph ^ 1u);
        consume(1, 2 * it + 1);
        produce(1, 2 * it + 3);
        if (!rdy2) mbar_wait(mb, ph ^ 1u);
    }
    {   // tail: chunks 14 (slot 0, phase 1) and 15 (slot 1, phase 1)
        uint32_t rdy = mbar_poll(mb + 16, 1u);
        consume(0, NCHUNK - 2);
        if (!rdy) mbar_wait(mb + 16, 1u);
        consume(1, NCHUNK - 1);
    }

    // Epilogue: fold BN + the reference's double-added bias into scale/shift
    float4 ga = *reinterpret_cast<const float4*>(gamma + f0);
    float4 bt = *reinterpret_cast<const float4*>(beta + f0);
    float4 mn = *reinterpret_cast<const float4*>(mean + f0);
    float4 vr = *reinterpret_cast<const float4*>(var + f0);
    float4 bi = *reinterpret_cast<const float4*>(bias + (size_t)l * NF + f0);

    float scv[4], shv[4];
    scv[0] = ga.x * rsqrtf(vr.x + 1e-3f); shv[0] = bt.x + (2.f * bi.x - mn.x) * scv[0];
    scv[1] = ga.y * rsqrtf(vr.y + 1e-3f); shv[1] = bt.y + (2.f * bi.y - mn.y) * scv[1];
    scv[2] = ga.z * rsqrtf(vr.z + 1e-3f); shv[2] = bt.z + (2.f * bi.z - mn.z) * scv[2];
    scv[3] = ga.w * rsqrtf(vr.w + 1e-3f); shv[3] = bt.w + (2.f * bi.w - mn.w) * scv[3];

    float* dstbase = SECOND ? out : (float*)g_h;

    #pragma unroll
    for (int b = 0; b < 8; ++b) {
        float2 v0 = unpk(acc[b][0]);            // (f0, f0+1)
        float2 v1 = unpk(acc[b][1]);            // (f0+2, f0+3)
        const int bl = b0 + b;

        float o0 = v0.x * scv[0] + shv[0];
        float o1 = v0.y * scv[1] + shv[1];
        float o2 = v1.x * scv[2] + shv[2];
        float o3 = v1.y * scv[3] + shv[3];
        if (SECOND) {
            float4 r = *reinterpret_cast<const float4*>(residx + ((size_t)bl * NL + l) * NC + f0);
            o0 += r.x; o1 += r.y; o2 += r.z; o3 += r.w;
        }
        o0 = lky(o0); o1 = lky(o1); o2 = lky(o2); o3 = lky(o3);

        *reinterpret_cast<float4*>(dstbase + ((size_t)bl * NL + l) * NC + f0) =
            make_float4(o0, o1, o2, o3);
    }
}

extern "C" void kernel_launch(void* const* d_in, const int* in_sizes, int n_in,
                              void* d_out, int out_size) {
    (void)in_sizes; (void)n_in; (void)out_size;
    const float* x   = (const float*)d_in[0];
    const float* k1  = (const float*)d_in[1];
    const float* b1  = (const float*)d_in[2];
    const float* g1  = (const float*)d_in[3];
    const float* be1 = (const float*)d_in[4];
    const float* m1  = (const float*)d_in[5];
    const float* v1  = (const float*)d_in[6];
    const float* k2  = (const float*)d_in[7];
    const float* b2  = (const float*)d_in[8];
    const float* g2  = (const float*)d_in[9];
    const float* be2 = (const float*)d_in[10];
    const float* m2  = (const float*)d_in[11];
    const float* v2  = (const float*)d_in[12];
    float* out = (float*)d_out;

    cudaFuncSetAttribute(lc_kernel<false>, cudaFuncAttributeMaxDynamicSharedMemorySize, SMEM_TOTAL);
    cudaFuncSetAttribute(lc_kernel<true >, cudaFuncAttributeMaxDynamicSharedMemorySize, SMEM_TOTAL);

    dim3 grid(NL / TL);
    lc_kernel<false><<<grid, 256, SMEM_TOTAL>>>(x, k1, b1, g1, be1, m1, v1, nullptr, nullptr);
    lc_kernel<true ><<<grid, 256, SMEM_TOTAL>>>(nullptr, k2, b2, g2, be2, m2, v2, x, out);
}

// round 17
// speedup vs baseline: 1.2512x; 1.2512x over previous
#include <cuda.h>
#include <cuda_runtime.h>
#include <cstdint>

#define NB 32
#define NL 8192
#define NC 32
#define NF 32
#define TL 8                  // positions per CTA (= warps per CTA)
#define ROWS (TL + 3)         // halo: 2 before, 1 after
#define PAD 36                // 16B-aligned batch rows -> LDS.128 x loads
#define NSTG 2                // pipeline stages
#define CCH 2                 // channels per chunk
#define NCHUNK (NC / CCH)     // 16 chunks
#define TAPB 2048             // per-tap per-stage block: 8 pos x 256 B
#define STG_BYTES (5 * TAPB)  // 10240 B per stage
#define HALF_TX (5 * 4 * 256) // 5120 B per half-CTA produce
#define MBAR_OFF 0            // 2 halves x 64 B
#define WS_OFF 512
#define SX_OFF (WS_OFF + NSTG * STG_BYTES)    // 20992
#define SX_BYTES (ROWS * NC * PAD * 4)        // 50688
#define SMEM_TOTAL (SX_OFF + SX_BYTES)        // 71680 -> 3 CTAs/SM

// Inter-layer scratch for h = leaky(bn(lc1(x)))
__device__ float g_h[(size_t)NB * NL * NC];

typedef unsigned long long ull;

__device__ __forceinline__ ull dup2(float w) {
    ull r; unsigned int u = __float_as_uint(w);
    asm("mov.b64 %0, {%1, %1};" : "=l"(r) : "r"(u));
    return r;
}
__device__ __forceinline__ void fma2(ull& d, ull a, ull b) {
    asm("fma.rn.f32x2 %0, %1, %2, %0;" : "+l"(d) : "l"(a), "l"(b));
}
__device__ __forceinline__ float2 unpk(ull v) {
    float2 f;
    asm("mov.b64 {%0, %1}, %2;" : "=f"(f.x), "=f"(f.y) : "l"(v));
    return f;
}
__device__ __forceinline__ float lky(float v) { return v >= 0.f ? v : 0.3f * v; }

__device__ __forceinline__ uint32_t s2u(const void* p) {
    uint32_t a;
    asm("{ .reg .u64 t; cvta.to.shared.u64 t, %1; cvt.u32.u64 %0, t; }" : "=r"(a) : "l"(p));
    return a;
}
__device__ __forceinline__ void mbar_init(uint32_t a, uint32_t c) {
    asm volatile("mbarrier.init.shared.b64 [%0], %1;" :: "r"(a), "r"(c) : "memory");
}
__device__ __forceinline__ void mbar_arrive(uint32_t a) {
    asm volatile("mbarrier.arrive.shared.b64 _, [%0];" :: "r"(a) : "memory");
}
__device__ __forceinline__ void mbar_expect(uint32_t a, uint32_t tx) {
    asm volatile("mbarrier.arrive.expect_tx.shared.b64 _, [%0], %1;" :: "r"(a), "r"(tx) : "memory");
}
__device__ __forceinline__ uint32_t mbar_poll(uint32_t a, uint32_t ph) {
    uint32_t r;
    asm volatile(
        "{\n\t.reg .pred P;\n\t"
        "mbarrier.test_wait.parity.shared.b64 P, [%1], %2;\n\t"
        "selp.b32 %0, 1, 0, P;\n\t}"
        : "=r"(r) : "r"(a), "r"(ph) : "memory");
    return r;
}
__device__ __forceinline__ void mbar_wait(uint32_t a, uint32_t ph) {
    asm volatile(
        "{\n\t.reg .pred P;\n"
        "W%=:\n\tmbarrier.try_wait.parity.shared.b64 P, [%0], %1, 0x989680;\n\t"
        "@P bra D%=;\n\tbra W%=;\nD%=:\n\t}"
        :: "r"(a), "r"(ph) : "memory");
}
__device__ __forceinline__ void tma2d(uint32_t dst, const CUtensorMap* tm,
                                      int x, int y, uint32_t mbar) {
    asm volatile(
        "cp.async.bulk.tensor.2d.shared::cta.global.tile.mbarrier::complete_tx::bytes "
        "[%0], [%1, {%2, %3}], [%4];"
        :: "r"(dst), "l"(tm), "r"(x), "r"(y), "r"(mbar) : "memory");
}

// 16-fma2 update: 4 batch-pairs (2x LDS.128) times 4 dup'd weights
__device__ __forceinline__ void tap_fma(ull acc[4][4], const float* xr,
                                        ull d0, ull d1, ull d2, ull d3) {
    ulonglong2 xa = *reinterpret_cast<const ulonglong2*>(xr);
    ulonglong2 xb = *reinterpret_cast<const ulonglong2*>(xr + 4);
    fma2(acc[0][0], xa.x, d0); fma2(acc[0][1], xa.x, d1);
    fma2(acc[0][2], xa.x, d2); fma2(acc[0][3], xa.x, d3);
    fma2(acc[1][0], xa.y, d0); fma2(acc[1][1], xa.y, d1);
    fma2(acc[1][2], xa.y, d2); fma2(acc[1][3], xa.y, d3);
    fma2(acc[2][0], xb.x, d0); fma2(acc[2][1], xb.x, d1);
    fma2(acc[2][2], xb.x, d2); fma2(acc[2][3], xb.x, d3);
    fma2(acc[3][0], xb.y, d0); fma2(acc[3][1], xb.y, d1);
    fma2(acc[3][2], xb.y, d2); fma2(acc[3][3], xb.y, d3);
}

template <bool SECOND>
__global__ void __launch_bounds__(256, 3)
lc_kernel(const float* __restrict__ in,
          const float* __restrict__ bias,    // [L, F]
          const float* __restrict__ gamma,
          const float* __restrict__ beta,
          const float* __restrict__ mean,
          const float* __restrict__ var,
          const float* __restrict__ residx,  // original x (L2 only)
          float* __restrict__ out,
          const __grid_constant__ CUtensorMap tmap)  // weights [5*L rows, C*F cols]
{
    extern __shared__ __align__(128) char smem[];
    const uint32_t sbase = s2u(smem);
    float* sx = reinterpret_cast<float*>(smem + SX_OFF);

    const int tid  = threadIdx.x;
    const int warp = tid >> 5;
    const int lane = tid & 31;
    const int l0   = blockIdx.x * TL;
    const int l    = l0 + warp;                 // one warp = one position
    const int h    = warp >> 2;                 // half-CTA (4 positions each)
    const bool prodw = ((warp & 3) == 0);       // warps 0 and 4 produce

    // Per-half rings: full[s] at h*64+s*16 (count 1: expect_tx),
    //                 empty[s] at +8 (count 4: the half's warps)
    if (tid < 4) {
        int hh = tid >> 1, s = tid & 1;
        mbar_init(sbase + MBAR_OFF + hh * 64 + s * 16, 1);
        mbar_init(sbase + MBAR_OFF + hh * 64 + s * 16 + 8, 4);
    }
    __syncthreads();

    const uint32_t mbh = sbase + MBAR_OFF + h * 64;

    // One 2D TMA per (tap): box 64 cols x 4 rows; rows = tap*NL + l0 + h*4
    auto produce = [&](int slot, int chunk) {
        if (prodw && lane == 0) {
            mbar_expect(mbh + slot * 16, HALF_TX);
            #pragma unroll
            for (int k = 0; k < 5; ++k)
                tma2d(sbase + WS_OFF + slot * STG_BYTES + k * TAPB + h * 1024,
                      &tmap, chunk * (CCH * NF), k * NL + l0 + h * 4,
                      mbh + slot * 16);
        }
    };

    // Prologue: both slots in flight (fresh barriers, no empty wait)
    produce(0, 0);
    produce(1, 1);

    // Stage input tile [lp][c][b] while weight DMA is in flight
    const float* src = SECOND ? (const float*)g_h : in;
    for (int idx = tid; idx < NB * ROWS * NC; idx += 256) {
        int b   = idx / (ROWS * NC);
        int rem = idx - b * (ROWS * NC);
        int lp  = rem >> 5;
        int c   = rem & 31;
        int gl  = (l0 + lp - 2) & (NL - 1);
        sx[(lp * NC + c) * PAD + b] = src[((size_t)b * NL + gl) * NC + c];
    }
    __syncthreads();

    const int f0 = (lane & 7) << 2;             // 4 filters / thread
    const int b0 = (lane >> 3) << 3;            // 8 batches / thread

    ull acc[4][4];
    #pragma unroll
    for (int i = 0; i < 4; ++i)
        #pragma unroll
        for (int j = 0; j < 4; ++j) acc[i][j] = 0ull;

    const float* xrB = sx + warp * (NC * PAD) + b0;
    // Stage layout: [tap][pos][64 floats]; this warp's chunk at tap*TAPB + warp*256
    const char*  wsb = smem + WS_OFF + warp * 256 + f0 * 4;

    auto consume = [&](int slot, int chunk) {
        const char* wp0 = wsb + slot * STG_BYTES;
        #pragma unroll
        for (int cc = 0; cc < CCH; ++cc) {
            const int c = chunk * CCH + cc;
            const float4 wA = *reinterpret_cast<const float4*>(wp0 + 0 * TAPB + cc * 128);
            const float4 wB = *reinterpret_cast<const float4*>(wp0 + 1 * TAPB + cc * 128);
            const float4 wC = *reinterpret_cast<const float4*>(wp0 + 2 * TAPB + cc * 128);
            const float4 wD = *reinterpret_cast<const float4*>(wp0 + 3 * TAPB + cc * 128);
            const float4 wE = *reinterpret_cast<const float4*>(wp0 + 4 * TAPB + cc * 128);
            tap_fma(acc, xrB + 2 * NC * PAD + c * PAD,
                    dup2(wA.x + wB.x), dup2(wA.y + wB.y),
                    dup2(wA.z + wB.z), dup2(wA.w + wB.w));
            tap_fma(acc, xrB + 1 * NC * PAD + c * PAD, dup2(wC.x), dup2(wC.y), dup2(wC.z), dup2(wC.w));
            tap_fma(acc, xrB + 3 * NC * PAD + c * PAD, dup2(wD.x), dup2(wD.y), dup2(wD.z), dup2(wD.w));
            tap_fma(acc, xrB + 0 * NC * PAD + c * PAD, dup2(wE.x), dup2(wE.y), dup2(wE.z), dup2(wE.w));
        }
    };

    // Wait for chunk 0 (slot 0, phase 0)
    mbar_wait(mbh, 0u);

    // Steady state, unrolled by 2 (poll-ahead, late wait)
    #pragma unroll 1
    for (int it = 0; it < NCHUNK / 2 - 1; ++it) {
        const uint32_t ph = (uint32_t)(it & 1);

        // even chunk 2it (slot 0, phase ph)
        uint32_t rdy = mbar_poll(mbh + 16, ph);
        consume(0, 2 * it);
        if (lane == 0) mbar_arrive(mbh + 8);               // empty0
        if (prodw) { mbar_wait(mbh + 8, ph); produce(0, 2 * it + 2); }
        if (!rdy) mbar_wait(mbh + 16, ph);

        // odd chunk 2it+1 (slot 1, phase ph)
        uint32_t rdy2 = mbar_poll(mbh, ph ^ 1u);
        consume(1, 2 * it + 1);
        if (lane == 0) mbar_arrive(mbh + 24);              // empty1
        if (prodw) { mbar_wait(mbh + 24, ph); produce(1, 2 * it + 3); }
        if (!rdy2) mbar_wait(mbh, ph ^ 1u);
    }
    {   // tail: chunks 14 (slot 0, phase 1) and 15 (slot 1, phase 1)
        uint32_t rdy = mbar_poll(mbh + 16, 1u);
        consume(0, NCHUNK - 2);
        if (!rdy) mbar_wait(mbh + 16, 1u);
        consume(1, NCHUNK - 1);
    }

    // Epilogue: fold BN + the reference's double-added bias into scale/shift
    float4 ga = *reinterpret_cast<const float4*>(gamma + f0);
    float4 bt = *reinterpret_cast<const float4*>(beta + f0);
    float4 mn = *reinterpret_cast<const float4*>(mean + f0);
    float4 vr = *reinterpret_cast<const float4*>(var + f0);
    float4 bi = *reinterpret_cast<const float4*>(bias + (size_t)l * NF + f0);

    float scv[4], shv[4];
    scv[0] = ga.x * rsqrtf(vr.x + 1e-3f); shv[0] = bt.x + (2.f * bi.x - mn.x) * scv[0];
    scv[1] = ga.y * rsqrtf(vr.y + 1e-3f); shv[1] = bt.y + (2.f * bi.y - mn.y) * scv[1];
    scv[2] = ga.z * rsqrtf(vr.z + 1e-3f); shv[2] = bt.z + (2.f * bi.z - mn.z) * scv[2];
    scv[3] = ga.w * rsqrtf(vr.w + 1e-3f); shv[3] = bt.w + (2.f * bi.w - mn.w) * scv[3];

    float* dstbase = SECOND ? out : (float*)g_h;

    #pragma unroll
    for (int bp = 0; bp < 4; ++bp) {
        float2 v[4];
        #pragma unroll
        for (int ff = 0; ff < 4; ++ff) v[ff] = unpk(acc[bp][ff]);

        const int bl = b0 + 2 * bp;
        float o0[4], o1[4];
        #pragma unroll
        for (int ff = 0; ff < 4; ++ff) {
            o0[ff] = v[ff].x * scv[ff] + shv[ff];
            o1[ff] = v[ff].y * scv[ff] + shv[ff];
        }
        if (SECOND) {
            float4 r0 = *reinterpret_cast<const float4*>(residx + ((size_t)bl * NL + l) * NC + f0);
            float4 r1 = *reinterpret_cast<const float4*>(residx + ((size_t)(bl + 1) * NL + l) * NC + f0);
            o0[0] += r0.x; o0[1] += r0.y; o0[2] += r0.z; o0[3] += r0.w;
            o1[0] += r1.x; o1[1] += r1.y; o1[2] += r1.z; o1[3] += r1.w;
        }
        #pragma unroll
        for (int ff = 0; ff < 4; ++ff) { o0[ff] = lky(o0[ff]); o1[ff] = lky(o1[ff]); }

        float* d0 = dstbase + ((size_t)bl * NL + l) * NC + f0;
        float* d1 = dstbase + ((size_t)(bl + 1) * NL + l) * NC + f0;
        *reinterpret_cast<float4*>(d0) = make_float4(o0[0], o0[1], o0[2], o0[3]);
        *reinterpret_cast<float4*>(d1) = make_float4(o1[0], o1[1], o1[2], o1[3]);
    }
}

// Host: build a 2D tensor map over weights [5*L rows, C*F cols], fp32,
// row stride 4096 B. Driver entry point fetched via the runtime (no -lcuda).
typedef CUresult (*PFN_encodeTiled)(
    CUtensorMap*, CUtensorMapDataType, cuuint32_t, void*,
    const cuuint64_t*, const cuuint64_t*, const cuuint32_t*, const cuuint32_t*,
    CUtensorMapInterleave, CUtensorMapSwizzle, CUtensorMapL2promotion,
    CUtensorMapFloatOOBfill);

static void make_wmap(CUtensorMap* tm, const float* w) {
    void* fp = nullptr;
    cudaGetDriverEntryPoint("cuTensorMapEncodeTiled", &fp, cudaEnableDefault);
    PFN_encodeTiled enc = (PFN_encodeTiled)fp;
    cuuint64_t dims[2]    = { (cuuint64_t)(NC * NF), (cuuint64_t)(5 * NL) };
    cuuint64_t strides[1] = { (cuuint64_t)(NC * NF * 4) };
    cuuint32_t box[2]     = { CCH * NF, 4 };    // 64 cols x 4 rows = 1 KB
    cuuint32_t estr[2]    = { 1, 1 };
    enc(tm, CU_TENSOR_MAP_DATA_TYPE_FLOAT32, 2, (void*)w,
        dims, strides, box, estr,
        CU_TENSOR_MAP_INTERLEAVE_NONE, CU_TENSOR_MAP_SWIZZLE_NONE,
        CU_TENSOR_MAP_L2_PROMOTION_L2_128B, CU_TENSOR_MAP_FLOAT_OOB_FILL_NONE);
}

extern "C" void kernel_launch(void* const* d_in, const int* in_sizes, int n_in,
                              void* d_out, int out_size) {
    (void)in_sizes; (void)n_in; (void)out_size;
    const float* x   = (const float*)d_in[0];
    const float* k1  = (const float*)d_in[1];
    const float* b1  = (const float*)d_in[2];
    const float* g1  = (const float*)d_in[3];
    const float* be1 = (const float*)d_in[4];
    const float* m1  = (const float*)d_in[5];
    const float* v1  = (const float*)d_in[6];
    const float* k2  = (const float*)d_in[7];
    const float* b2  = (const float*)d_in[8];
    const float* g2  = (const float*)d_in[9];
    const float* be2 = (const float*)d_in[10];
    const float* m2  = (const float*)d_in[11];
    const float* v2  = (const float*)d_in[12];
    float* out = (float*)d_out;

    CUtensorMap tm1, tm2;
    make_wmap(&tm1, k1);
    make_wmap(&tm2, k2);

    cudaFuncSetAttribute(lc_kernel<false>, cudaFuncAttributeMaxDynamicSharedMemorySize, SMEM_TOTAL);
    cudaFuncSetAttribute(lc_kernel<true >, cudaFuncAttributeMaxDynamicSharedMemorySize, SMEM_TOTAL);

    dim3 grid(NL / TL);
    lc_kernel<false><<<grid, 256, SMEM_TOTAL>>>(x, b1, g1, be1, m1, v1, nullptr, nullptr, tm1);
    lc_kernel<true ><<<grid, 256, SMEM_TOTAL>>>(nullptr, b2, g2, be2, m2, v2, x, out, tm2);
}